// round 10
// baseline (speedup 1.0000x reference)
#include <cuda_runtime.h>
#include <cstdint>

#define GD 256
#define GH 256
#define GW 256
#define NT 16
#define TS 16
#define RWIN 6
#define DHW_I 16777216
#define NTILES 4096
#define CAP 512
#define MAXN 32768
#define CHUNK 64

// zero-initialized at module load; splat_tiles self-resets cursors each run
__device__ int    g_cursors[NTILES];
__device__ uint2  g_pairs  [NTILES * CAP];
__device__ float4 g_params [MAXN * 3];  // {cx,cy,cz,C00},{C11,C22,S01,S02},{S12,wr,wi,-}

// ---------------------------------------------------------------------------
__device__ __forceinline__ bool gbounds(float cx, float cy, float cz, float r,
                                        int& x0, int& x1, int& y0, int& y1,
                                        int& z0, int& z1)
{
    const int bx = (int)floorf(cx);
    const int by = (int)floorf(cy);
    const int bz = (int)floorf(cz);
    x0 = max((int)floorf(cx - r), max(bx - RWIN, 0));
    x1 = min((int)ceilf (cx + r), min(bx + RWIN, GD - 1));
    y0 = max((int)floorf(cy - r), max(by - RWIN, 0));
    y1 = min((int)ceilf (cy + r), min(by + RWIN, GH - 1));
    z0 = max((int)floorf(cz - r), max(bz - RWIN, 0));
    z1 = min((int)ceilf (cz + r), min(bz + RWIN, GW - 1));
    return (x0 <= x1) && (y0 <= y1) && (z0 <= z1);
}

// ---------------------------------------------------------------------------
// Binning + per-Gaussian param packing. Pair record: (gid, packed bounds +
// 8-bit warp-window mask). Warp windows in splat: wid&3 = x-window (4 wide),
// wid>>2 = y-window (8 tall).
// ---------------------------------------------------------------------------
__global__ __launch_bounds__(64)
void scatter_kernel(const float* __restrict__ center,
                    const float* __restrict__ covinv,
                    const float* __restrict__ dens_r,
                    const float* __restrict__ dens_i,
                    const float* __restrict__ radius, int N)
{
    int g = blockIdx.x * blockDim.x + threadIdx.x;
    if (g >= N) return;

    const float cx = center[3*g+0], cy = center[3*g+1], cz = center[3*g+2];

    g_params[3*g+0] = make_float4(cx, cy, cz, covinv[9*g+0]);
    g_params[3*g+1] = make_float4(covinv[9*g+4], covinv[9*g+8],
                                  covinv[9*g+1] + covinv[9*g+3],
                                  covinv[9*g+2] + covinv[9*g+6]);
    g_params[3*g+2] = make_float4(covinv[9*g+5] + covinv[9*g+7],
                                  dens_r[g], dens_i[g], 0.0f);

    int x0, x1, y0, y1, z0, z1;
    if (!gbounds(cx, cy, cz, radius[g], x0, x1, y0, y1, z0, z1)) return;

    for (int tx = x0 >> 4; tx <= (x1 >> 4); ++tx) {
        const int xb = tx * TS;
        const unsigned lx0 = (unsigned)max(x0 - xb, 0);
        const unsigned lx1 = (unsigned)min(x1 - xb, TS - 1);
        unsigned xm = 0;
        #pragma unroll
        for (int w = 0; w < 4; ++w)
            if (lx0 <= (unsigned)(4*w + 3) && lx1 >= (unsigned)(4*w)) xm |= 1u << w;
        for (int ty = y0 >> 4; ty <= (y1 >> 4); ++ty) {
            const int yb = ty * TS;
            const unsigned ly0 = (unsigned)max(y0 - yb, 0);
            const unsigned ly1 = (unsigned)min(y1 - yb, TS - 1);
            unsigned m8 = 0;
            if (ly0 <= 7u) m8 |= xm;
            if (ly1 >= 8u) m8 |= xm << 4;
            for (int tz = z0 >> 4; tz <= (z1 >> 4); ++tz) {
                const int zb = tz * TS;
                const unsigned lz0 = (unsigned)max(z0 - zb, 0);
                const unsigned lz1 = (unsigned)min(z1 - zb, TS - 1);
                const unsigned bb = lx0 | (lx1 << 4) | (ly0 << 8) |
                                    (ly1 << 12) | (lz0 << 16) | (lz1 << 20) |
                                    (m8 << 24);
                const int tile = (tx * NT + ty) * NT + tz;
                const int slot = atomicAdd(&g_cursors[tile], 1);
                if (slot < CAP)
                    g_pairs[tile * CAP + slot] = make_uint2((unsigned)g, bb);
            }
        }
    }
}

// ---------------------------------------------------------------------------
// One CTA per 16^3 tile. Each thread owns its (x,y) column's FULL 16-z extent
// in REGISTERS (float2 acc[16]) -> zero smem crossbar traffic in the hot loop.
//  * warp = 4x * 8y window; 8-bit pair mask for cheap warp skip
//  * 4 z-quads guarded by WARP-UNIFORM branches (lz bounds are pair-level)
//  * per quad: L re-anchored (2 FMA Horner), forward-differenced inside;
//    xy/z/threshold masks folded into one FSEL; ex2.ftz(-1000) == +0.0f
//  * writeout: regs -> smem (conflict-free) -> coalesced float4 stores
//  * resets its own cursor for the next graph replay
// ---------------------------------------------------------------------------
__global__ __launch_bounds__(256, 3)
void splat_tiles_kernel(const float* __restrict__ half_shape,
                        float* __restrict__ out)
{
    const int b  = blockIdx.x;
    const int tz = b & 15, ty = (b >> 4) & 15, tx = b >> 8;
    const int xb = tx * TS, yb = ty * TS, zb = tz * TS;

    const int tid  = threadIdx.x;
    const int wid  = tid >> 5;
    const int lane = tid & 31;
    const int wx   = (wid & 3) * 4;
    const int wy   = (wid >> 2) * 8;
    const int lx   = wx + (lane >> 3);
    const int ly   = wy + (lane & 7);
    const int col  = wid * 32 + lane;
    const unsigned wbit = 1u << wid;

    __shared__ float4   sAccP[8][256];     // 32 KB: writeout staging only
    __shared__ float4   sp4[CHUNK * 3];
    __shared__ unsigned sbnd[CHUNK];
    __shared__ int      scnt;

    float2 acc[16];
    #pragma unroll
    for (int z = 0; z < 16; ++z) acc[z] = make_float2(0.f, 0.f);

    if (tid == 0) {
        scnt = min(g_cursors[b], CAP);
        g_cursors[b] = 0;                  // self-reset for next replay
    }
    __syncthreads();

    const float ihx = 1.0f / half_shape[0];
    const float ihy = 1.0f / half_shape[1];
    const float e   = 1.0f / half_shape[2];

    const int cnt = scnt;
    const uint2* __restrict__ bucket = g_pairs + b * CAP;

    const float fvx = (float)(xb + lx);
    const float fvy = (float)(yb + ly);

    const float h   = -0.72134752044448170f;   // -0.5 * log2(e)
    const float Lth = -6.49212768400033530f;   // 9 * h (Md<=9 <=> L>=Lth)

    for (int base = 0; base < cnt; base += CHUNK) {
        const int n = min(cnt - base, CHUNK);
        __syncthreads();
        if (tid < n) {
            const uint2 pr = bucket[base + tid];
            const int g = (int)pr.x;
            sp4[3*tid+0] = g_params[3*g+0];
            sp4[3*tid+1] = g_params[3*g+1];
            sp4[3*tid+2] = g_params[3*g+2];
            sbnd[tid] = pr.y;
        }
        __syncthreads();

        for (int i = 0; i < n; ++i) {
            const unsigned bbp = sbnd[i];
            if (!((bbp >> 24) & wbit)) continue;      // warp skip

            const int lx0 = bbp & 15,         lx1 = (bbp >> 4) & 15;
            const int ly0 = (bbp >> 8) & 15,  ly1 = (bbp >> 12) & 15;
            const int lz0 = (bbp >> 16) & 15, lz1 = (bbp >> 20) & 15;
            const bool xyok = (lx >= lx0) & (lx <= lx1) &
                              (ly >= ly0) & (ly <= ly1);

            const float4 p0 = sp4[3*i+0];
            const float4 p1 = sp4[3*i+1];
            const float4 p2 = sp4[3*i+2];
            const float cx = p0.x, cy = p0.y, cz = p0.z, C00 = p0.w;
            const float C11 = p1.x, C22 = p1.y, S01 = p1.z, S02 = p1.w;
            const float S12 = p2.x, wr = p2.y, wi = p2.z;

            const float dx = (fvx - cx) * ihx;
            const float dy = (fvy - cy) * ihy;

            const float Bxy = fmaf(S02, dx, S12 * dy);
            const float Cxy = fmaf(fmaf(C00, dx, S01 * dy), dx,
                                   C11 * dy * dy);

            // quadratic in tile-local z (anchor z = 0 of tile)
            const float dzb = ((float)zb - cz) * e;
            const float A = C22 * e * e;
            const float B = e * fmaf(2.0f * C22, dzb, Bxy);
            const float C = fmaf(C22, dzb * dzb, fmaf(Bxy, dzb, Cxy));

            const float hA = h * A, hB = h * B, hC = h * C;
            const float dd = 2.0f * hA;

            #pragma unroll
            for (int q = 0; q < 4; ++q) {
                const int z0 = q * 4;
                // warp-uniform quad guard (lz bounds are pair-level)
                if (lz1 >= z0 && lz0 <= z0 + 3) {
                    const float zf = (float)z0;
                    float L  = fmaf(fmaf(hA, zf, hB), zf, hC);
                    float dL = fmaf(hA, 2.0f * zf + 1.0f, hB);
                    #pragma unroll
                    for (int k = 0; k < 4; ++k) {
                        const int z = z0 + k;
                        const bool val = xyok & (z >= lz0) & (z <= lz1) &
                                         (L >= Lth);
                        const float Ls = val ? L : -1000.0f;
                        float w;
                        asm("ex2.approx.ftz.f32 %0, %1;" : "=f"(w) : "f"(Ls));
                        acc[z].x = fmaf(w, wr, acc[z].x);
                        acc[z].y = fmaf(w, wi, acc[z].y);
                        L += dL;
                        dL += dd;
                    }
                }
            }
        }
    }

    // dump register columns to smem (conflict-free: warp -> 512B contiguous)
    __syncthreads();
    #pragma unroll
    for (int zp = 0; zp < 8; ++zp)
        sAccP[zp][col] = make_float4(acc[2*zp].x,   acc[2*zp].y,
                                     acc[2*zp+1].x, acc[2*zp+1].y);
    __syncthreads();

    // writeout: thread qi=(c,k) writes z quad [4k,4k+3] of column c.
    #pragma unroll
    for (int j = 0; j < 4; ++j) {
        const int qi = tid + 256 * j;
        const int c  = qi >> 2;
        const int k  = qi & 3;
        const float4 a  = sAccP[2*k + 0][c];
        const float4 bq = sAccP[2*k + 1][c];
        const int cw = c >> 5, cl = c & 31;
        const int gx = xb + (cw & 3) * 4 + (cl >> 3);
        const int gy = yb + (cw >> 2) * 8 + (cl & 7);
        const int idx = (gx * GH + gy) * GW + zb + 4 * k;
        *(float4*)(out + idx)         = make_float4(a.x, a.z, bq.x, bq.z);
        *(float4*)(out + idx + DHW_I) = make_float4(a.y, a.w, bq.y, bq.w);
    }
}

// ---------------------------------------------------------------------------
extern "C" void kernel_launch(void* const* d_in, const int* in_sizes, int n_in,
                              void* d_out, int out_size) {
    const float* center     = (const float*)d_in[0];
    const float* covinv     = (const float*)d_in[1];
    const float* dens_r     = (const float*)d_in[2];
    const float* dens_i     = (const float*)d_in[3];
    const float* radius     = (const float*)d_in[4];
    const float* half_shape = (const float*)d_in[5];

    float* out = (float*)d_out;
    const int N = in_sizes[2];

    scatter_kernel<<<(N + 63) / 64, 64>>>(center, covinv, dens_r, dens_i,
                                          radius, N);
    splat_tiles_kernel<<<NTILES, 256>>>(half_shape, out);
}